// round 1
// baseline (speedup 1.0000x reference)
#include <cuda_runtime.h>

#define PH   8
#define NN   8
#define KK   64
#define CC   128
#define HH   128
#define WW   128
#define MAX_NIJ (PH * 128)   // supports MW up to 128 (actual max is 64 by construction)

// Per-(i,j) bilinear record lives in shared memory: 4 clamped offsets + 4 masked weights.

__global__ void __launch_bounds__(256)
bbp_kernel(const float* __restrict__ x,
           const float* __restrict__ boxes,
           float* __restrict__ feats,
           float* __restrict__ widths,
           int MW)
{
    __shared__ int4   s_off[MAX_NIJ];
    __shared__ float4 s_w[MAX_NIJ];

    const int blk = blockIdx.x;          // ((n*K + k)*2 + d)
    const int d   = blk & 1;
    const int k   = (blk >> 1) & (KK - 1);
    const int n   = blk >> 7;            // / (2*KK)
    const int tid = threadIdx.x;

    // ---- box parameters (uniform per block) ----
    const float4 b = reinterpret_cast<const float4*>(boxes)[n * KK + k];
    const float xmin = b.x, ymin = b.y, xmax = b.z, ymax = b.w;
    const bool valid = !(xmin == 0.f && ymin == 0.f && xmax == 0.f && ymax == 0.f);
    const float bw = valid ? (xmax - xmin) : 1.f;
    const float bh = valid ? (ymax - ymin) : 1.f;
    const bool wide = bw > bh;
    const float ratio = wide ? (bw / bh) : (bh / bw);
    const int   width = valid ? (int)ceilf(ratio * (float)PH) : 0;
    const float wf    = (float)(width > 2 ? width : 2);
    const float inv_wf1 = 1.0f / (wf - 1.0f);
    const float inv_ph1 = 1.0f / (float)(PH - 1);

    const int nij = PH * MW;

    // ---- phase 1: precompute bilinear records for all (i,j) ----
    for (int e = tid; e < nij; e += blockDim.x) {
        const int i = e / MW;
        const int j = e - i * MW;

        float4 w = make_float4(0.f, 0.f, 0.f, 0.f);
        int4   o = make_int4(0, 0, 0, 0);

        if (j < width) {
            float fi = (float)i, fj = (float)j;
            if (d) {                       // flipped grid within valid columns
                fi = (float)(PH - 1) - fi;
                fj = (wf - 1.0f) - fj;
            }
            float px, py;
            if (wide) {
                px = xmin + fj * bw * inv_wf1;
                py = ymin + fi * bh * inv_ph1;
            } else {
                px = xmin + fi * bw * inv_ph1;
                py = ymin + (wf - fj) * bh * inv_wf1;
            }
            // grid_sample (align_corners=False) unnormalize cancels exactly:
            const float ix = px - 0.5f;
            const float iy = py - 0.5f;
            const float x0f = floorf(ix), y0f = floorf(iy);
            const int x0 = (int)x0f, y0 = (int)y0f;
            const int x1 = x0 + 1,   y1 = y0 + 1;
            const float dx = ix - x0f, dy = iy - y0f;
            const float wx0 = 1.f - dx, wx1 = dx;
            const float wy0 = 1.f - dy, wy1 = dy;

            const bool vx0 = (x0 >= 0) & (x0 < WW);
            const bool vx1 = (x1 >= 0) & (x1 < WW);
            const bool vy0 = (y0 >= 0) & (y0 < HH);
            const bool vy1 = (y1 >= 0) & (y1 < HH);

            w.x = (vx0 & vy0) ? wx0 * wy0 : 0.f;   // (x0,y0)
            w.y = (vx1 & vy0) ? wx1 * wy0 : 0.f;   // (x1,y0)
            w.z = (vx0 & vy1) ? wx0 * wy1 : 0.f;   // (x0,y1)
            w.w = (vx1 & vy1) ? wx1 * wy1 : 0.f;   // (x1,y1)

            const int xc0 = min(max(x0, 0), WW - 1);
            const int xc1 = min(max(x1, 0), WW - 1);
            const int yc0 = min(max(y0, 0), HH - 1);
            const int yc1 = min(max(y1, 0), HH - 1);
            o.x = yc0 * WW + xc0;
            o.y = yc0 * WW + xc1;
            o.z = yc1 * WW + xc0;
            o.w = yc1 * WW + xc1;
        }
        s_off[e] = o;
        s_w[e]   = w;
    }
    __syncthreads();

    // ---- phase 2: stream all C * PH * MW outputs, j innermost (coalesced) ----
    const float* __restrict__ xb = x + (size_t)n * CC * (HH * WW);
    float* __restrict__ outb = feats + (size_t)blk * CC * nij;
    const int total = CC * nij;

    int ij = tid;
    int c  = 0;
    while (ij >= nij) { ij -= nij; ++c; }   // handles nij < blockDim
    const float* xc = xb + (size_t)c * (HH * WW);

    for (int e = tid; e < total; e += blockDim.x) {
        const int4   o = s_off[ij];
        const float4 w = s_w[ij];
        const float v = w.x * __ldg(xc + o.x)
                      + w.y * __ldg(xc + o.y)
                      + w.z * __ldg(xc + o.z)
                      + w.w * __ldg(xc + o.w);
        outb[e] = v;

        ij += blockDim.x;
        while (ij >= nij) { ij -= nij; ++c; xc = xb + (size_t)c * (HH * WW); }
    }

    if (tid == 0) {
        widths[(size_t)(n * KK + k) * 2 + d] = (float)width;
    }
}

extern "C" void kernel_launch(void* const* d_in, const int* in_sizes, int n_in,
                              void* d_out, int out_size)
{
    const float* x     = (const float*)d_in[0];
    const float* boxes = (const float*)d_in[1];
    float* out = (float*)d_out;

    // out = concat(feats (N,K,2,C,PH,MW), widths (N,K,2))
    const long long widths_elems = (long long)NN * KK * 2;               // 1024
    const long long per_mw       = (long long)NN * KK * 2 * CC * PH;     // 1048576
    int MW = (int)(((long long)out_size - widths_elems) / per_mw);
    if (MW < 1) MW = 1;
    if (MW > 128) MW = 128;

    float* feats  = out;
    float* widths = out + (size_t)per_mw * MW;

    const int blocks = NN * KK * 2;   // 1024
    bbp_kernel<<<blocks, 256>>>(x, boxes, feats, widths, MW);
}

// round 2
// speedup vs baseline: 1.7049x; 1.7049x over previous
#include <cuda_runtime.h>

#define PH   8
#define NN   8
#define KK   64
#define CC   128
#define HH   128
#define WW   128

#define CSPLIT 8                 // channel chunks per (n,k) box
#define CPB   (CC / CSPLIT)      // 16 channels per block
#define TPB   256
#define RPT   2                  // records per thread (nij <= 512)

// One block handles one (n,k) box (BOTH directions d=0,1) and CPB channels.
// Each thread owns up to RPT (i,j) bilinear records in registers.
// d=1 output is the exact flip of d=0 within valid columns, so each gathered
// value is written twice (once straight, once flipped); padding writes zeros.

__global__ void __launch_bounds__(TPB)
bbp_kernel(const float* __restrict__ x,
           const float* __restrict__ boxes,
           float* __restrict__ feats,
           float* __restrict__ widths,
           int MW)
{
    const int nk  = blockIdx.x;            // n*KK + k
    const int n   = nk >> 6;
    const int cc0 = blockIdx.y * CPB;      // first channel of this block's chunk
    const int tid = threadIdx.x;

    // ---- box parameters (uniform per block) ----
    const float4 b = reinterpret_cast<const float4*>(boxes)[nk];
    const float xmin = b.x, ymin = b.y, xmax = b.z, ymax = b.w;
    const bool valid_box = !(xmin == 0.f && ymin == 0.f && xmax == 0.f && ymax == 0.f);
    const float bw = valid_box ? (xmax - xmin) : 1.f;
    const float bh = valid_box ? (ymax - ymin) : 1.f;
    const bool wide = bw > bh;
    const float ratio = wide ? (bw / bh) : (bh / bw);
    const int   width = valid_box ? (int)ceilf(ratio * (float)PH) : 0;
    const float wf    = (float)(width > 2 ? width : 2);
    const float inv_wf1 = 1.0f / (wf - 1.0f);
    const float inv_ph1 = 1.0f / (float)(PH - 1);

    const int nij = PH * MW;

    // ---- per-thread register records ----
    int4   r_off[RPT];
    float4 r_w[RPT];
    int    r_dst1[RPT];   // d=1 destination index within a channel plane
    bool   r_val[RPT];
    bool   r_act[RPT];    // element exists (e < nij)

    #pragma unroll
    for (int r = 0; r < RPT; ++r) {
        const int e = tid + r * TPB;
        r_act[r] = (e < nij);
        r_val[r] = false;
        r_off[r] = make_int4(0, 0, 0, 0);
        r_w[r]   = make_float4(0.f, 0.f, 0.f, 0.f);
        r_dst1[r] = e;
        if (!r_act[r]) continue;
        const int i = e / MW;
        const int j = e - i * MW;
        if (j < width) {
            r_val[r]  = true;
            r_dst1[r] = (PH - 1 - i) * MW + (width - 1 - j);
            float px, py;
            const float fi = (float)i, fj = (float)j;
            if (wide) {
                px = xmin + fj * bw * inv_wf1;
                py = ymin + fi * bh * inv_ph1;
            } else {
                px = xmin + fi * bw * inv_ph1;
                py = ymin + (wf - fj) * bh * inv_wf1;
            }
            const float ix = px - 0.5f;          // grid normalize/unnormalize cancels
            const float iy = py - 0.5f;
            const float x0f = floorf(ix), y0f = floorf(iy);
            const int x0 = (int)x0f, y0 = (int)y0f;
            const int x1 = x0 + 1,   y1 = y0 + 1;
            const float dx = ix - x0f, dy = iy - y0f;
            const float wx0 = 1.f - dx, wx1 = dx;
            const float wy0 = 1.f - dy, wy1 = dy;
            const bool vx0 = (x0 >= 0) & (x0 < WW);
            const bool vx1 = (x1 >= 0) & (x1 < WW);
            const bool vy0 = (y0 >= 0) & (y0 < HH);
            const bool vy1 = (y1 >= 0) & (y1 < HH);
            r_w[r].x = (vx0 & vy0) ? wx0 * wy0 : 0.f;
            r_w[r].y = (vx1 & vy0) ? wx1 * wy0 : 0.f;
            r_w[r].z = (vx0 & vy1) ? wx0 * wy1 : 0.f;
            r_w[r].w = (vx1 & vy1) ? wx1 * wy1 : 0.f;
            const int xc0 = min(max(x0, 0), WW - 1);
            const int xc1 = min(max(x1, 0), WW - 1);
            const int yc0 = min(max(y0, 0), HH - 1);
            const int yc1 = min(max(y1, 0), HH - 1);
            r_off[r].x = yc0 * WW + xc0;
            r_off[r].y = yc0 * WW + xc1;
            r_off[r].z = yc1 * WW + xc0;
            r_off[r].w = yc1 * WW + xc1;
        }
    }

    // ---- stream channels ----
    // feats layout: (N, K, 2, C, PH, MW)
    const float* __restrict__ xbase = x + ((size_t)n * CC + cc0) * (HH * WW);
    float* __restrict__ out0 = feats + (((size_t)nk * 2 + 0) * CC + cc0) * nij;
    float* __restrict__ out1 = feats + (((size_t)nk * 2 + 1) * CC + cc0) * nij;

    for (int c = 0; c < CPB; ++c) {
        const float* __restrict__ xc = xbase + (size_t)c * (HH * WW);
        float* __restrict__ o0 = out0 + (size_t)c * nij;
        float* __restrict__ o1 = out1 + (size_t)c * nij;
        #pragma unroll
        for (int r = 0; r < RPT; ++r) {
            if (!r_act[r]) continue;
            const int e = tid + r * TPB;
            float v = 0.f;
            if (r_val[r]) {
                const int4   o = r_off[r];
                const float4 w = r_w[r];
                v = w.x * __ldg(xc + o.x)
                  + w.y * __ldg(xc + o.y)
                  + w.z * __ldg(xc + o.z)
                  + w.w * __ldg(xc + o.w);
            }
            o0[e]         = v;   // straight
            o1[r_dst1[r]] = v;   // flipped (valid) or same-slot zero (padding)
        }
    }

    if (tid == 0 && blockIdx.y == 0) {
        widths[(size_t)nk * 2 + 0] = (float)width;
        widths[(size_t)nk * 2 + 1] = (float)width;
    }
}

extern "C" void kernel_launch(void* const* d_in, const int* in_sizes, int n_in,
                              void* d_out, int out_size)
{
    const float* x     = (const float*)d_in[0];
    const float* boxes = (const float*)d_in[1];
    float* out = (float*)d_out;

    // out = concat(feats (N,K,2,C,PH,MW), widths (N,K,2))
    const long long widths_elems = (long long)NN * KK * 2;               // 1024
    const long long per_mw       = (long long)NN * KK * 2 * CC * PH;     // 1048576
    int MW = (int)(((long long)out_size - widths_elems) / per_mw);
    if (MW < 1) MW = 1;
    if (MW > 64) MW = 64;   // nij <= 512 by construction (ratio < 8)

    float* feats  = out;
    float* widths = out + (size_t)per_mw * MW;

    dim3 grid(NN * KK, CSPLIT);
    bbp_kernel<<<grid, TPB>>>(x, boxes, feats, widths, MW);
}

// round 3
// speedup vs baseline: 2.5510x; 1.4963x over previous
#include <cuda_runtime.h>

#define PH   8
#define NN   8
#define KK   64
#define CC   128
#define HH   128
#define WW   128

#define CSPLIT 16                // channel chunks per (n,k) box
#define CPB   (CC / CSPLIT)      // 8 channels per block
#define TPB   512                // one (i,j) record per thread (nij <= 512)

// One block: one (n,k) box, BOTH directions d=0/1, CPB channels.
// Each thread owns exactly one (i,j) bilinear record in registers.
// d=1 output is the exact flip of d=0 within valid columns; each gathered
// value is stored twice. Streaming stores (__stwt) keep x resident in L2.

__global__ void __launch_bounds__(TPB)
bbp_kernel(const float* __restrict__ x,
           const float* __restrict__ boxes,
           float* __restrict__ feats,
           float* __restrict__ widths,
           int MW)
{
    const int nk  = blockIdx.x;            // n*KK + k
    const int n   = nk >> 6;
    const int cc0 = blockIdx.y * CPB;
    const int tid = threadIdx.x;

    // ---- box parameters (uniform per block) ----
    const float4 b = reinterpret_cast<const float4*>(boxes)[nk];
    const float xmin = b.x, ymin = b.y, xmax = b.z, ymax = b.w;
    const bool valid_box = !(xmin == 0.f && ymin == 0.f && xmax == 0.f && ymax == 0.f);
    const float bw = valid_box ? (xmax - xmin) : 1.f;
    const float bh = valid_box ? (ymax - ymin) : 1.f;
    const bool wide = bw > bh;
    const float ratio = wide ? (bw / bh) : (bh / bw);
    const int   width = valid_box ? (int)ceilf(ratio * (float)PH) : 0;
    const float wf    = (float)(width > 2 ? width : 2);
    const float inv_wf1 = 1.0f / (wf - 1.0f);
    const float inv_ph1 = 1.0f / (float)(PH - 1);

    const int nij = PH * MW;
    const int e   = tid;
    if (e >= nij) {
        if (tid == 0) {} // nothing; widths handled below by tid 0 which is always < nij
        return;
    }

    const int i = e / MW;
    const int j = e - i * MW;
    const bool val = (j < width);

    int4   off = make_int4(0, 0, 0, 0);
    float4 w   = make_float4(0.f, 0.f, 0.f, 0.f);
    int    dst1 = e;

    if (val) {
        dst1 = (PH - 1 - i) * MW + (width - 1 - j);
        float px, py;
        const float fi = (float)i, fj = (float)j;
        if (wide) {
            px = xmin + fj * bw * inv_wf1;
            py = ymin + fi * bh * inv_ph1;
        } else {
            px = xmin + fi * bw * inv_ph1;
            py = ymin + (wf - fj) * bh * inv_wf1;
        }
        const float ix = px - 0.5f;   // grid normalize/unnormalize cancels exactly
        const float iy = py - 0.5f;
        const float x0f = floorf(ix), y0f = floorf(iy);
        const int x0 = (int)x0f, y0 = (int)y0f;
        const int x1 = x0 + 1,   y1 = y0 + 1;
        const float dx = ix - x0f, dy = iy - y0f;
        const float wx0 = 1.f - dx, wx1 = dx;
        const float wy0 = 1.f - dy, wy1 = dy;
        const bool vx0 = (x0 >= 0) & (x0 < WW);
        const bool vx1 = (x1 >= 0) & (x1 < WW);
        const bool vy0 = (y0 >= 0) & (y0 < HH);
        const bool vy1 = (y1 >= 0) & (y1 < HH);
        w.x = (vx0 & vy0) ? wx0 * wy0 : 0.f;
        w.y = (vx1 & vy0) ? wx1 * wy0 : 0.f;
        w.z = (vx0 & vy1) ? wx0 * wy1 : 0.f;
        w.w = (vx1 & vy1) ? wx1 * wy1 : 0.f;
        const int xc0 = min(max(x0, 0), WW - 1);
        const int xc1 = min(max(x1, 0), WW - 1);
        const int yc0 = min(max(y0, 0), HH - 1);
        const int yc1 = min(max(y1, 0), HH - 1);
        off.x = yc0 * WW + xc0;
        off.y = yc0 * WW + xc1;
        off.z = yc1 * WW + xc0;
        off.w = yc1 * WW + xc1;
    }

    // ---- stream channels (fully unrolled: 8 x 4 independent gathers) ----
    const float* __restrict__ xbase = x + ((size_t)n * CC + cc0) * (HH * WW);
    float* __restrict__ out0 = feats + (((size_t)nk * 2 + 0) * CC + cc0) * nij + e;
    float* __restrict__ out1 = feats + (((size_t)nk * 2 + 1) * CC + cc0) * nij + dst1;

    float v[CPB];
    if (val) {
        #pragma unroll
        for (int c = 0; c < CPB; ++c) {
            const float* __restrict__ xc = xbase + (size_t)c * (HH * WW);
            v[c] = w.x * __ldg(xc + off.x)
                 + w.y * __ldg(xc + off.y)
                 + w.z * __ldg(xc + off.z)
                 + w.w * __ldg(xc + off.w);
        }
    } else {
        #pragma unroll
        for (int c = 0; c < CPB; ++c) v[c] = 0.f;
    }

    #pragma unroll
    for (int c = 0; c < CPB; ++c) {
        __stwt(out0 + (size_t)c * nij, v[c]);   // straight
        __stwt(out1 + (size_t)c * nij, v[c]);   // flipped (or same-slot zero pad)
    }

    if (tid == 0 && blockIdx.y == 0) {
        widths[(size_t)nk * 2 + 0] = (float)width;
        widths[(size_t)nk * 2 + 1] = (float)width;
    }
}

extern "C" void kernel_launch(void* const* d_in, const int* in_sizes, int n_in,
                              void* d_out, int out_size)
{
    const float* x     = (const float*)d_in[0];
    const float* boxes = (const float*)d_in[1];
    float* out = (float*)d_out;

    // out = concat(feats (N,K,2,C,PH,MW), widths (N,K,2))
    const long long widths_elems = (long long)NN * KK * 2;               // 1024
    const long long per_mw       = (long long)NN * KK * 2 * CC * PH;     // 1048576
    int MW = (int)(((long long)out_size - widths_elems) / per_mw);
    if (MW < 1) MW = 1;
    if (MW > 64) MW = 64;   // nij <= 512 by construction (ratio < 8)

    float* feats  = out;
    float* widths = out + (size_t)per_mw * MW;

    dim3 grid(NN * KK, CSPLIT);
    bbp_kernel<<<grid, TPB>>>(x, boxes, feats, widths, MW);
}